// round 4
// baseline (speedup 1.0000x reference)
#include <cuda_runtime.h>
#include <cstdint>

#define DIM   512
#define BATCH 32
#define TT    2048
#define G4    2048              // 4*DIM
#define NBLK  128               // persistent blocks for recurrence
#define RTHR  256

// ---------------- device scratch (no allocations allowed) ----------------
__device__ __align__(16) float g_xg[(size_t)TT * G4 * BATCH];   // [t][n][b]
__device__ __align__(16) float g_hbuf[2][DIM * BATCH];          // [k4][b][4]
__device__ unsigned g_flag[NBLK * 8];   // one 32B sector per block
__device__ unsigned g_gen;

typedef unsigned long long ull;

// ---------------- f32x2 helpers ----------------
__device__ __forceinline__ ull f2fma(ull a, ull b, ull c){
    ull d; asm("fma.rn.f32x2 %0, %1, %2, %3;" : "=l"(d) : "l"(a), "l"(b), "l"(c)); return d;
}
__device__ __forceinline__ ull pk2(float lo, float hi){
    ull r; asm("mov.b64 %0, {%1, %2};" : "=l"(r) : "f"(lo), "f"(hi)); return r;
}
__device__ __forceinline__ float2 upk(ull v){
    float2 f; asm("mov.b64 {%0, %1}, %2;" : "=f"(f.x), "=f"(f.y) : "l"(v)); return f;
}
__device__ __forceinline__ float hadd(ull v){ float2 f = upk(v); return f.x + f.y; }

__device__ __forceinline__ float sigf(float x){ return 1.0f / (1.0f + __expf(-x)); }
__device__ __forceinline__ float tanhfast(float x){
    float e = __expf(2.0f * x);              // inf-safe at both ends
    return 1.0f - 2.0f / (e + 1.0f);
}

// ---------------- scoped sync primitives ----------------
__device__ __forceinline__ void st_release(unsigned* p, unsigned v){
    asm volatile("st.release.gpu.global.u32 [%0], %1;" :: "l"(p), "r"(v) : "memory");
}
__device__ __forceinline__ unsigned ld_acquire(unsigned* p){
    unsigned v;
    asm volatile("ld.acquire.gpu.global.u32 %0, [%1];" : "=r"(v) : "l"(p) : "memory");
    return v;
}

// =====================================================================
// Kernel 1: xg[t][n][b] = sum_k x[b][t][k]*W_ih[n][k] + b_ih[n] + b_hh[n]
// M = 65536 (m = t*32 + b), N = 2048, K = 512. 128x128x8 tile, f32x2.
// Block (0,0) also re-initializes recurrence state each launch.
// =====================================================================
__global__ void __launch_bounds__(256) gemm_xg_kernel(
    const float* __restrict__ x, const float* __restrict__ Wih,
    const float* __restrict__ bih, const float* __restrict__ bhh)
{
    __shared__ float As[8][128];
    __shared__ float Bs[8][128];
    const int tid = threadIdx.x;

    if (blockIdx.x == 0 && blockIdx.y == 0){     // init (runs before rec kernel)
        for (int i = tid; i < DIM * BATCH; i += 256) g_hbuf[0][i] = 0.0f;
        for (int i = tid; i < NBLK; i += 256) g_flag[i * 8] = 0u;
        if (tid == 0) g_gen = 0u;
    }

    const int bn0 = blockIdx.x * 128;
    const int bm0 = blockIdx.y * 128;
    const int tm0 = (tid >> 4) * 8;
    const int c4  = (tid & 15) * 4;

    const int lr = tid >> 1;
    const int lk = (tid & 1) * 4;
    const int m  = bm0 + lr;
    const float* ap = x + (size_t)(m & 31) * ((size_t)TT * DIM) + (size_t)(m >> 5) * DIM + lk;
    const float* bp = Wih + (size_t)(bn0 + lr) * DIM + lk;

    ull c2[4][8];
    #pragma unroll
    for (int i = 0; i < 4; i++)
        #pragma unroll
        for (int j = 0; j < 8; j++) c2[i][j] = 0ULL;

    float4 av = *(const float4*)ap;
    float4 bv = *(const float4*)bp;

    for (int k0 = 0; k0 < DIM; k0 += 8){
        As[lk+0][lr]=av.x; As[lk+1][lr]=av.y; As[lk+2][lr]=av.z; As[lk+3][lr]=av.w;
        Bs[lk+0][lr]=bv.x; Bs[lk+1][lr]=bv.y; Bs[lk+2][lr]=bv.z; Bs[lk+3][lr]=bv.w;
        __syncthreads();
        if (k0 + 8 < DIM){
            av = *(const float4*)(ap + k0 + 8);
            bv = *(const float4*)(bp + k0 + 8);
        }
        #pragma unroll
        for (int kk = 0; kk < 8; kk++){
            const ulonglong2* arow = (const ulonglong2*)&As[kk][tm0];
            ulonglong2 a01 = arow[0];
            ulonglong2 a23 = arow[1];
            float4 bl = *(const float4*)&Bs[kk][c4];
            float4 bh = *(const float4*)&Bs[kk][c4 + 64];
            ull bd[8];
            bd[0]=pk2(bl.x,bl.x); bd[1]=pk2(bl.y,bl.y); bd[2]=pk2(bl.z,bl.z); bd[3]=pk2(bl.w,bl.w);
            bd[4]=pk2(bh.x,bh.x); bd[5]=pk2(bh.y,bh.y); bd[6]=pk2(bh.z,bh.z); bd[7]=pk2(bh.w,bh.w);
            #pragma unroll
            for (int j = 0; j < 8; j++){
                c2[0][j] = f2fma(a01.x, bd[j], c2[0][j]);
                c2[1][j] = f2fma(a01.y, bd[j], c2[1][j]);
                c2[2][j] = f2fma(a23.x, bd[j], c2[2][j]);
                c2[3][j] = f2fma(a23.y, bd[j], c2[3][j]);
            }
        }
        __syncthreads();
    }

    float bias[8];
    #pragma unroll
    for (int j = 0; j < 8; j++){
        int n = bn0 + c4 + (j & 3) + ((j >> 2) << 6);
        bias[j] = bih[n] + bhh[n];
    }
    #pragma unroll
    for (int i = 0; i < 8; i++){
        int mg = bm0 + tm0 + i;
        size_t obase = (size_t)(mg >> 5) * ((size_t)G4 * BATCH) + (size_t)(mg & 31);
        #pragma unroll
        for (int j = 0; j < 8; j++){
            float2 p = upk(c2[i >> 1][j]);
            float v = (i & 1) ? p.y : p.x;
            int n = bn0 + c4 + (j & 3) + ((j >> 2) << 6);
            g_xg[obase + (size_t)n * BATCH] = v + bias[j];
        }
    }
}

// =====================================================================
// Kernel 2: persistent recurrence. 128 blocks x 256 threads.
// warp = kh (k-eighth, 64 k each); lane = (bq = l&7, dl = l>>3).
// Thread computes 4 gates x 4 batches (bq+8j) x 64 k for dim dg=bx*4+dl.
// W slice in shared (padded rows, broadcast reads); h read from global
// L2 with __ldcg; k-reduction via padded shared buffer; pointwise +
// c-state in threads tid<128. Flag/gen grid barrier per step.
// =====================================================================
__global__ void __launch_bounds__(RTHR) lstm_rec_kernel(
    const float* __restrict__ Whh, float* __restrict__ out)
{
    extern __shared__ float sm[];
    float* shW = sm;                       // 16 rows x 516 floats (padded)
    float* shR = sm + 16 * 516;            // [16][8][33] partials

    const int tid = threadIdx.x;
    const int bx  = blockIdx.x;
    const int kh  = tid >> 5;              // warp id = k-eighth
    const int lane= tid & 31;
    const int bq  = lane & 7;
    const int dl  = lane >> 3;

    // Load this block's 16 W_hh rows into padded shared (once).
    for (int idx = tid; idx < 16 * 128; idx += RTHR){
        int rl = idx >> 7;                 // g*4 + dloc
        int k4 = idx & 127;
        int g = rl >> 2, dloc = rl & 3;
        *(float4*)(shW + rl * 516 + k4 * 4) =
            *(const float4*)(Whh + (size_t)(g * DIM + bx * 4 + dloc) * DIM + k4 * 4);
    }

    const ulonglong2* w0 = (const ulonglong2*)(shW + (0*4 + dl) * 516 + kh * 64);
    const ulonglong2* w1 = (const ulonglong2*)(shW + (1*4 + dl) * 516 + kh * 64);
    const ulonglong2* w2 = (const ulonglong2*)(shW + (2*4 + dl) * 516 + kh * 64);
    const ulonglong2* w3 = (const ulonglong2*)(shW + (3*4 + dl) * 516 + kh * 64);
    const int hbase = kh * 512 + bq;       // float4 index into g_hbuf

    // pointwise ownership (tid < 128): (pb, pd)
    const int pb = tid & 31;
    const int pd = tid >> 5;               // valid when tid < 128
    const int dgp = bx * 4 + pd;
    const int pbh = pb >> 3;
    const int pli = pd * 8 + (pb & 7);
    float* outp = out + (size_t)pb * ((size_t)TT * DIM) + dgp;
    const float* xgb = g_xg + (size_t)pb;
    const int hwidx = (bx * 32 + pb) * 4 + pd;   // float index in g_hbuf

    float cc = 0.0f;
    __syncthreads();                       // W ready

    for (int t = 0; t < TT; t++){
        // xg prefetch (independent of h)
        float xv0, xv1, xv2, xv3;
        if (tid < 128){
            const float* xt = xgb + (size_t)t * ((size_t)G4 * BATCH);
            xv0 = __ldcg(xt + (size_t)(0*DIM + dgp) * BATCH);
            xv1 = __ldcg(xt + (size_t)(1*DIM + dgp) * BATCH);
            xv2 = __ldcg(xt + (size_t)(2*DIM + dgp) * BATCH);
            xv3 = __ldcg(xt + (size_t)(3*DIM + dgp) * BATCH);
        }

        // ---- partial gates over this thread's 64-k slice, 4 b, 4 gates ----
        const float4* hb = (const float4*)g_hbuf[t & 1];
        ull acc[4][4];
        #pragma unroll
        for (int g = 0; g < 4; g++)
            #pragma unroll
            for (int j = 0; j < 4; j++) acc[g][j] = 0ULL;

        #pragma unroll 2
        for (int i = 0; i < 16; i++){
            int hi = hbase + i * 32;
            ulonglong2 h0 = __ldcg((const ulonglong2*)(hb + hi));
            ulonglong2 h1 = __ldcg((const ulonglong2*)(hb + hi + 8));
            ulonglong2 h2 = __ldcg((const ulonglong2*)(hb + hi + 16));
            ulonglong2 h3 = __ldcg((const ulonglong2*)(hb + hi + 24));
            ulonglong2 v0 = w0[i], v1 = w1[i], v2 = w2[i], v3 = w3[i];
            acc[0][0]=f2fma(h0.x,v0.x,acc[0][0]); acc[0][0]=f2fma(h0.y,v0.y,acc[0][0]);
            acc[0][1]=f2fma(h1.x,v0.x,acc[0][1]); acc[0][1]=f2fma(h1.y,v0.y,acc[0][1]);
            acc[0][2]=f2fma(h2.x,v0.x,acc[0][2]); acc[0][2]=f2fma(h2.y,v0.y,acc[0][2]);
            acc[0][3]=f2fma(h3.x,v0.x,acc[0][3]); acc[0][3]=f2fma(h3.y,v0.y,acc[0][3]);
            acc[1][0]=f2fma(h0.x,v1.x,acc[1][0]); acc[1][0]=f2fma(h0.y,v1.y,acc[1][0]);
            acc[1][1]=f2fma(h1.x,v1.x,acc[1][1]); acc[1][1]=f2fma(h1.y,v1.y,acc[1][1]);
            acc[1][2]=f2fma(h2.x,v1.x,acc[1][2]); acc[1][2]=f2fma(h2.y,v1.y,acc[1][2]);
            acc[1][3]=f2fma(h3.x,v1.x,acc[1][3]); acc[1][3]=f2fma(h3.y,v1.y,acc[1][3]);
            acc[2][0]=f2fma(h0.x,v2.x,acc[2][0]); acc[2][0]=f2fma(h0.y,v2.y,acc[2][0]);
            acc[2][1]=f2fma(h1.x,v2.x,acc[2][1]); acc[2][1]=f2fma(h1.y,v2.y,acc[2][1]);
            acc[2][2]=f2fma(h2.x,v2.x,acc[2][2]); acc[2][2]=f2fma(h2.y,v2.y,acc[2][2]);
            acc[2][3]=f2fma(h3.x,v2.x,acc[2][3]); acc[2][3]=f2fma(h3.y,v2.y,acc[2][3]);
            acc[3][0]=f2fma(h0.x,v3.x,acc[3][0]); acc[3][0]=f2fma(h0.y,v3.y,acc[3][0]);
            acc[3][1]=f2fma(h1.x,v3.x,acc[3][1]); acc[3][1]=f2fma(h1.y,v3.y,acc[3][1]);
            acc[3][2]=f2fma(h2.x,v3.x,acc[3][2]); acc[3][2]=f2fma(h2.y,v3.y,acc[3][2]);
            acc[3][3]=f2fma(h3.x,v3.x,acc[3][3]); acc[3][3]=f2fma(h3.y,v3.y,acc[3][3]);
        }

        // ---- write partials: shR[j16 = g*4+bh][kh][dl*8+bq], stride 33 ----
        #pragma unroll
        for (int g = 0; g < 4; g++)
            #pragma unroll
            for (int j = 0; j < 4; j++)
                shR[(g*4 + j) * 264 + kh * 33 + lane] = hadd(acc[g][j]);
        __syncthreads();

        // ---- reduce over kh + pointwise (tid < 128) ----
        if (tid < 128){
            float gs[4];
            #pragma unroll
            for (int g = 0; g < 4; g++){
                const float* r = shR + (g*4 + pbh) * 264 + pli;
                float s = r[0];
                #pragma unroll
                for (int k = 1; k < 8; k++) s += r[k * 33];
                gs[g] = s;
            }
            float gi = gs[0] + xv0;
            float gf = gs[1] + xv1;
            float gg = gs[2] + xv2;
            float go = gs[3] + xv3;
            float iv = sigf(gi), fv = sigf(gf), gv = tanhfast(gg), ov = sigf(go);
            cc = fv * cc + iv * gv;
            float hv = ov * tanhfast(cc);
            g_hbuf[(t + 1) & 1][hwidx] = hv;
            outp[(size_t)t * DIM] = hv;
        }

        // ---- grid barrier: per-block flag + master gen broadcast ----
        __syncthreads();                         // h store + shR reads done
        if (tid == 0) st_release(&g_flag[bx * 8], (unsigned)(t + 1));
        if (bx == 0){
            if (tid < 128){
                while (ld_acquire(&g_flag[tid * 8]) < (unsigned)(t + 1)) { }
            }
            __syncthreads();
            if (tid == 0) st_release(&g_gen, (unsigned)(t + 1));
        } else {
            if (tid == 0){
                while (ld_acquire(&g_gen) < (unsigned)(t + 1)) { }
            }
            __syncthreads();
        }
    }
}

// =====================================================================
extern "C" void kernel_launch(void* const* d_in, const int* in_sizes, int n_in,
                              void* d_out, int out_size)
{
    (void)in_sizes; (void)n_in; (void)out_size;
    const float* x    = (const float*)d_in[0];
    const float* Wih  = (const float*)d_in[1];
    const float* Whh  = (const float*)d_in[2];
    const float* bih  = (const float*)d_in[3];
    const float* bhh  = (const float*)d_in[4];
    float* out = (float*)d_out;

    // shW 16*516 + shR 16*264 = 12480 floats = 49920 bytes dynamic shared
    cudaFuncSetAttribute(lstm_rec_kernel,
                         cudaFuncAttributeMaxDynamicSharedMemorySize, 49920);

    dim3 ggrid(G4 / 128, (BATCH * TT) / 128);
    gemm_xg_kernel<<<ggrid, 256>>>(x, Wih, bih, bhh);
    lstm_rec_kernel<<<NBLK, RTHR, 49920>>>(Whh, out);
}

// round 5
// speedup vs baseline: 1.5119x; 1.5119x over previous
#include <cuda_runtime.h>
#include <cstdint>

#define DIM   512
#define BATCH 32
#define TT    2048
#define G4    2048              // 4*DIM
#define NBLK  128               // persistent blocks for recurrence
#define RTHR  256

// ---------------- device scratch (no allocations allowed) ----------------
__device__ __align__(16) float g_xg[(size_t)TT * G4 * BATCH];   // [t][n][b]
__device__ __align__(16) float g_hbuf[2][DIM * BATCH];          // [d>>2][b][d&3]
__device__ unsigned g_count;

typedef unsigned long long ull;

// ---------------- f32x2 helpers ----------------
__device__ __forceinline__ ull f2fma(ull a, ull b, ull c){
    ull d; asm("fma.rn.f32x2 %0, %1, %2, %3;" : "=l"(d) : "l"(a), "l"(b), "l"(c)); return d;
}
__device__ __forceinline__ ull pk2(float lo, float hi){
    ull r; asm("mov.b64 %0, {%1, %2};" : "=l"(r) : "f"(lo), "f"(hi)); return r;
}
__device__ __forceinline__ float2 upk(ull v){
    float2 f; asm("mov.b64 {%0, %1}, %2;" : "=f"(f.x), "=f"(f.y) : "l"(v)); return f;
}
__device__ __forceinline__ float hadd(ull v){ float2 f = upk(v); return f.x + f.y; }

__device__ __forceinline__ float sigf(float x){ return 1.0f / (1.0f + __expf(-x)); }
__device__ __forceinline__ float tanhfast(float x){
    float e = __expf(2.0f * x);              // inf-safe at both ends
    return 1.0f - 2.0f / (e + 1.0f);
}

// ---------------- scoped sync primitives ----------------
__device__ __forceinline__ void red_release_add(unsigned* p, unsigned v){
    asm volatile("red.release.gpu.global.add.u32 [%0], %1;" :: "l"(p), "r"(v) : "memory");
}
__device__ __forceinline__ unsigned ld_acquire(unsigned* p){
    unsigned v;
    asm volatile("ld.acquire.gpu.global.u32 %0, [%1];" : "=r"(v) : "l"(p) : "memory");
    return v;
}

// =====================================================================
// Kernel 1: xg[t][n][b] = sum_k x[b][t][k]*W_ih[n][k] + b_ih[n] + b_hh[n]
// M = 65536 (m = t*32 + b), N = 2048, K = 512. 128x128x8 tile, f32x2.
// Block (0,0) also re-initializes recurrence state each launch.
// =====================================================================
__global__ void __launch_bounds__(256) gemm_xg_kernel(
    const float* __restrict__ x, const float* __restrict__ Wih,
    const float* __restrict__ bih, const float* __restrict__ bhh)
{
    __shared__ float As[8][128];
    __shared__ float Bs[8][128];
    const int tid = threadIdx.x;

    if (blockIdx.x == 0 && blockIdx.y == 0){     // init (runs before rec kernel)
        for (int i = tid; i < DIM * BATCH; i += 256) g_hbuf[0][i] = 0.0f;
        if (tid == 0) g_count = 0u;
    }

    const int bn0 = blockIdx.x * 128;
    const int bm0 = blockIdx.y * 128;
    const int tm0 = (tid >> 4) * 8;
    const int c4  = (tid & 15) * 4;

    const int lr = tid >> 1;
    const int lk = (tid & 1) * 4;
    const int m  = bm0 + lr;
    const float* ap = x + (size_t)(m & 31) * ((size_t)TT * DIM) + (size_t)(m >> 5) * DIM + lk;
    const float* bp = Wih + (size_t)(bn0 + lr) * DIM + lk;

    ull c2[4][8];
    #pragma unroll
    for (int i = 0; i < 4; i++)
        #pragma unroll
        for (int j = 0; j < 8; j++) c2[i][j] = 0ULL;

    float4 av = *(const float4*)ap;
    float4 bv = *(const float4*)bp;

    for (int k0 = 0; k0 < DIM; k0 += 8){
        As[lk+0][lr]=av.x; As[lk+1][lr]=av.y; As[lk+2][lr]=av.z; As[lk+3][lr]=av.w;
        Bs[lk+0][lr]=bv.x; Bs[lk+1][lr]=bv.y; Bs[lk+2][lr]=bv.z; Bs[lk+3][lr]=bv.w;
        __syncthreads();
        if (k0 + 8 < DIM){
            av = *(const float4*)(ap + k0 + 8);
            bv = *(const float4*)(bp + k0 + 8);
        }
        #pragma unroll
        for (int kk = 0; kk < 8; kk++){
            const ulonglong2* arow = (const ulonglong2*)&As[kk][tm0];
            ulonglong2 a01 = arow[0];
            ulonglong2 a23 = arow[1];
            float4 bl = *(const float4*)&Bs[kk][c4];
            float4 bh = *(const float4*)&Bs[kk][c4 + 64];
            ull bd[8];
            bd[0]=pk2(bl.x,bl.x); bd[1]=pk2(bl.y,bl.y); bd[2]=pk2(bl.z,bl.z); bd[3]=pk2(bl.w,bl.w);
            bd[4]=pk2(bh.x,bh.x); bd[5]=pk2(bh.y,bh.y); bd[6]=pk2(bh.z,bh.z); bd[7]=pk2(bh.w,bh.w);
            #pragma unroll
            for (int j = 0; j < 8; j++){
                c2[0][j] = f2fma(a01.x, bd[j], c2[0][j]);
                c2[1][j] = f2fma(a01.y, bd[j], c2[1][j]);
                c2[2][j] = f2fma(a23.x, bd[j], c2[2][j]);
                c2[3][j] = f2fma(a23.y, bd[j], c2[3][j]);
            }
        }
        __syncthreads();
    }

    float bias[8];
    #pragma unroll
    for (int j = 0; j < 8; j++){
        int n = bn0 + c4 + (j & 3) + ((j >> 2) << 6);
        bias[j] = bih[n] + bhh[n];
    }
    #pragma unroll
    for (int i = 0; i < 8; i++){
        int mg = bm0 + tm0 + i;
        size_t obase = (size_t)(mg >> 5) * ((size_t)G4 * BATCH) + (size_t)(mg & 31);
        #pragma unroll
        for (int j = 0; j < 8; j++){
            float2 p = upk(c2[i >> 1][j]);
            float v = (i & 1) ? p.y : p.x;
            int n = bn0 + c4 + (j & 3) + ((j >> 2) << 6);
            g_xg[obase + (size_t)n * BATCH] = v + bias[j];
        }
    }
}

// =====================================================================
// Kernel 2: persistent recurrence. 128 blocks x 256 threads.
// warp = kh (k-eighth, 64 k each); lane = (bq = l&7, dl = l>>3).
// Thread computes 4 gates x 4 batches (bq+8j) x 64 k for dim dg=bx*4+dl.
// h staged into shared each step (coalesced, high-MLP) then read via
// broadcast LDS; W slice in padded shared rows; k-reduction via padded
// shared buffer; pointwise + c-state in tid<128. Single-counter grid
// barrier; out store + next-step xg prefetch overlap the barrier wait.
// =====================================================================
__global__ void __launch_bounds__(RTHR) lstm_rec_kernel(
    const float* __restrict__ Whh, float* __restrict__ out)
{
    extern __shared__ float sm[];
    float* shW = sm;                       // 16 rows x 516 floats (padded)
    float* shH = sm + 16 * 516;            // 16384 floats, same layout as g_hbuf
    float* shR = shH + 16384;              // [16][8][33] partials

    const int tid = threadIdx.x;
    const int bx  = blockIdx.x;
    const int kh  = tid >> 5;              // warp id = k-eighth
    const int lane= tid & 31;
    const int bq  = lane & 7;
    const int dl  = lane >> 3;

    // Load this block's 16 W_hh rows into padded shared (once).
    for (int idx = tid; idx < 16 * 128; idx += RTHR){
        int rl = idx >> 7;                 // g*4 + dloc
        int k4 = idx & 127;
        int g = rl >> 2, dloc = rl & 3;
        *(float4*)(shW + rl * 516 + k4 * 4) =
            *(const float4*)(Whh + (size_t)(g * DIM + bx * 4 + dloc) * DIM + k4 * 4);
    }

    const ulonglong2* w0 = (const ulonglong2*)(shW + (0*4 + dl) * 516 + kh * 64);
    const ulonglong2* w1 = (const ulonglong2*)(shW + (1*4 + dl) * 516 + kh * 64);
    const ulonglong2* w2 = (const ulonglong2*)(shW + (2*4 + dl) * 516 + kh * 64);
    const ulonglong2* w3 = (const ulonglong2*)(shW + (3*4 + dl) * 516 + kh * 64);
    const ulonglong2* hsh = ((const ulonglong2*)shH) + kh * 512 + bq;

    // pointwise ownership (tid < 128): (pb, pd)
    const int pb = tid & 31;
    const int pd = tid >> 5;               // valid when tid < 128
    const int dgp = bx * 4 + pd;
    const int pbh = pb >> 3;
    const int pli = pd * 8 + (pb & 7);
    float* outp = out + (size_t)pb * ((size_t)TT * DIM) + dgp;
    const float* xgb = g_xg + (size_t)pb;
    const int hwidx = (bx * 32 + pb) * 4 + pd;   // float index in g_hbuf

    float cc = 0.0f;

    // prefetch xg for t = 0
    float xv0 = 0.f, xv1 = 0.f, xv2 = 0.f, xv3 = 0.f;
    if (tid < 128){
        xv0 = __ldcg(xgb + (size_t)(0*DIM + dgp) * BATCH);
        xv1 = __ldcg(xgb + (size_t)(1*DIM + dgp) * BATCH);
        xv2 = __ldcg(xgb + (size_t)(2*DIM + dgp) * BATCH);
        xv3 = __ldcg(xgb + (size_t)(3*DIM + dgp) * BATCH);
    }
    __syncthreads();                       // W ready

    for (int t = 0; t < TT; t++){
        // ---- stage h_{t-1} into shared (coalesced, high-MLP) ----
        const float4* hsrc = (const float4*)g_hbuf[t & 1];
        float4* hdst = (float4*)shH;
        #pragma unroll
        for (int i = 0; i < 16; i++) hdst[tid + i * RTHR] = __ldcg(hsrc + tid + i * RTHR);
        __syncthreads();

        // ---- partial gates over this thread's 64-k slice, 4 b, 4 gates ----
        ull acc[4][4];
        #pragma unroll
        for (int g = 0; g < 4; g++)
            #pragma unroll
            for (int j = 0; j < 4; j++) acc[g][j] = 0ULL;

        #pragma unroll 4
        for (int i = 0; i < 16; i++){
            ulonglong2 h0 = hsh[i * 32];
            ulonglong2 h1 = hsh[i * 32 + 8];
            ulonglong2 h2 = hsh[i * 32 + 16];
            ulonglong2 h3 = hsh[i * 32 + 24];
            ulonglong2 v0 = w0[i], v1 = w1[i], v2 = w2[i], v3 = w3[i];
            acc[0][0]=f2fma(h0.x,v0.x,acc[0][0]); acc[0][0]=f2fma(h0.y,v0.y,acc[0][0]);
            acc[0][1]=f2fma(h1.x,v0.x,acc[0][1]); acc[0][1]=f2fma(h1.y,v0.y,acc[0][1]);
            acc[0][2]=f2fma(h2.x,v0.x,acc[0][2]); acc[0][2]=f2fma(h2.y,v0.y,acc[0][2]);
            acc[0][3]=f2fma(h3.x,v0.x,acc[0][3]); acc[0][3]=f2fma(h3.y,v0.y,acc[0][3]);
            acc[1][0]=f2fma(h0.x,v1.x,acc[1][0]); acc[1][0]=f2fma(h0.y,v1.y,acc[1][0]);
            acc[1][1]=f2fma(h1.x,v1.x,acc[1][1]); acc[1][1]=f2fma(h1.y,v1.y,acc[1][1]);
            acc[1][2]=f2fma(h2.x,v1.x,acc[1][2]); acc[1][2]=f2fma(h2.y,v1.y,acc[1][2]);
            acc[1][3]=f2fma(h3.x,v1.x,acc[1][3]); acc[1][3]=f2fma(h3.y,v1.y,acc[1][3]);
            acc[2][0]=f2fma(h0.x,v2.x,acc[2][0]); acc[2][0]=f2fma(h0.y,v2.y,acc[2][0]);
            acc[2][1]=f2fma(h1.x,v2.x,acc[2][1]); acc[2][1]=f2fma(h1.y,v2.y,acc[2][1]);
            acc[2][2]=f2fma(h2.x,v2.x,acc[2][2]); acc[2][2]=f2fma(h2.y,v2.y,acc[2][2]);
            acc[2][3]=f2fma(h3.x,v2.x,acc[2][3]); acc[2][3]=f2fma(h3.y,v2.y,acc[2][3]);
            acc[3][0]=f2fma(h0.x,v3.x,acc[3][0]); acc[3][0]=f2fma(h0.y,v3.y,acc[3][0]);
            acc[3][1]=f2fma(h1.x,v3.x,acc[3][1]); acc[3][1]=f2fma(h1.y,v3.y,acc[3][1]);
            acc[3][2]=f2fma(h2.x,v3.x,acc[3][2]); acc[3][2]=f2fma(h2.y,v3.y,acc[3][2]);
            acc[3][3]=f2fma(h3.x,v3.x,acc[3][3]); acc[3][3]=f2fma(h3.y,v3.y,acc[3][3]);
        }

        // ---- write partials: shR[g*4+j][kh][dl*8+bq], stride 33 ----
        #pragma unroll
        for (int g = 0; g < 4; g++)
            #pragma unroll
            for (int j = 0; j < 4; j++)
                shR[(g*4 + j) * 264 + kh * 33 + lane] = hadd(acc[g][j]);
        __syncthreads();

        float hv = 0.f;
        if (tid < 128){
            float gs[4];
            #pragma unroll
            for (int g = 0; g < 4; g++){
                const float* r = shR + (g*4 + pbh) * 264 + pli;
                float s = r[0];
                #pragma unroll
                for (int k = 1; k < 8; k++) s += r[k * 33];
                gs[g] = s;
            }
            float gi = gs[0] + xv0;
            float gf = gs[1] + xv1;
            float gg = gs[2] + xv2;
            float go = gs[3] + xv3;
            float iv = sigf(gi), fv = sigf(gf), gv = tanhfast(gg), ov = sigf(go);
            cc = fv * cc + iv * gv;
            hv = ov * tanhfast(cc);
            g_hbuf[(t + 1) & 1][hwidx] = hv;
        }

        // ---- arrival (release covers the h store) ----
        __syncthreads();
        if (tid == 0) red_release_add(&g_count, 1u);

        // ---- overlap barrier wait: out store + next xg prefetch ----
        if (tid < 128){
            outp[(size_t)t * DIM] = hv;
            if (t + 1 < TT){
                const float* xt = xgb + (size_t)(t + 1) * ((size_t)G4 * BATCH);
                xv0 = __ldcg(xt + (size_t)(0*DIM + dgp) * BATCH);
                xv1 = __ldcg(xt + (size_t)(1*DIM + dgp) * BATCH);
                xv2 = __ldcg(xt + (size_t)(2*DIM + dgp) * BATCH);
                xv3 = __ldcg(xt + (size_t)(3*DIM + dgp) * BATCH);
            }
        }

        // ---- wait for all arrivals ----
        if (tid == 0){
            const unsigned target = (unsigned)(t + 1) * NBLK;
            while (ld_acquire(&g_count) < target) { }
        }
        __syncthreads();
    }
}

// =====================================================================
extern "C" void kernel_launch(void* const* d_in, const int* in_sizes, int n_in,
                              void* d_out, int out_size)
{
    (void)in_sizes; (void)n_in; (void)out_size;
    const float* x    = (const float*)d_in[0];
    const float* Wih  = (const float*)d_in[1];
    const float* Whh  = (const float*)d_in[2];
    const float* bih  = (const float*)d_in[3];
    const float* bhh  = (const float*)d_in[4];
    float* out = (float*)d_out;

    // shW 16*516 + shH 16384 + shR 16*264 = 28864 floats = 115456 bytes
    cudaFuncSetAttribute(lstm_rec_kernel,
                         cudaFuncAttributeMaxDynamicSharedMemorySize, 115456);

    dim3 ggrid(G4 / 128, (BATCH * TT) / 128);
    gemm_xg_kernel<<<ggrid, 256>>>(x, Wih, bih, bhh);
    lstm_rec_kernel<<<NBLK, RTHR, 115456>>>(Whh, out);
}

// round 6
// speedup vs baseline: 1.5148x; 1.0019x over previous
#include <cuda_runtime.h>
#include <cstdint>

#define DIM   512
#define BATCH 32
#define TT    2048
#define G4    2048              // 4*DIM
#define NBLK  128               // persistent blocks for recurrence
#define RTHR  512

// ---------------- device scratch (no allocations allowed) ----------------
__device__ __align__(16) float g_xg[(size_t)TT * G4 * BATCH];   // [t][n][b]
__device__ __align__(16) float g_hbuf[2][DIM * BATCH];          // [d>>2][b][d&3]
__device__ unsigned g_count;

typedef unsigned long long ull;

// ---------------- f32x2 helpers ----------------
__device__ __forceinline__ ull f2fma(ull a, ull b, ull c){
    ull d; asm("fma.rn.f32x2 %0, %1, %2, %3;" : "=l"(d) : "l"(a), "l"(b), "l"(c)); return d;
}
__device__ __forceinline__ ull pk2(float lo, float hi){
    ull r; asm("mov.b64 %0, {%1, %2};" : "=l"(r) : "f"(lo), "f"(hi)); return r;
}
__device__ __forceinline__ float2 upk(ull v){
    float2 f; asm("mov.b64 {%0, %1}, %2;" : "=f"(f.x), "=f"(f.y) : "l"(v)); return f;
}
__device__ __forceinline__ float hadd(ull v){ float2 f = upk(v); return f.x + f.y; }

__device__ __forceinline__ float sigf(float x){ return 1.0f / (1.0f + __expf(-x)); }
__device__ __forceinline__ float tanhfast(float x){
    float e = __expf(2.0f * x);              // inf-safe at both ends
    return 1.0f - 2.0f / (e + 1.0f);
}

// ---------------- scoped sync primitives ----------------
__device__ __forceinline__ void red_release_add(unsigned* p, unsigned v){
    asm volatile("red.release.gpu.global.add.u32 [%0], %1;" :: "l"(p), "r"(v) : "memory");
}
__device__ __forceinline__ unsigned ld_acquire(unsigned* p){
    unsigned v;
    asm volatile("ld.acquire.gpu.global.u32 %0, [%1];" : "=r"(v) : "l"(p) : "memory");
    return v;
}

// =====================================================================
// Kernel 1: xg[t][n][b] = sum_k x[b][t][k]*W_ih[n][k] + b_ih[n] + b_hh[n]
// M = 65536 (m = t*32 + b), N = 2048, K = 512. 128x128x8 tile, f32x2.
// Block (0,0) also re-initializes recurrence state each launch.
// =====================================================================
__global__ void __launch_bounds__(256) gemm_xg_kernel(
    const float* __restrict__ x, const float* __restrict__ Wih,
    const float* __restrict__ bih, const float* __restrict__ bhh)
{
    __shared__ float As[8][128];
    __shared__ float Bs[8][128];
    const int tid = threadIdx.x;

    if (blockIdx.x == 0 && blockIdx.y == 0){     // init (runs before rec kernel)
        for (int i = tid; i < DIM * BATCH; i += 256) g_hbuf[0][i] = 0.0f;
        if (tid == 0) g_count = 0u;
    }

    const int bn0 = blockIdx.x * 128;
    const int bm0 = blockIdx.y * 128;
    const int tm0 = (tid >> 4) * 8;
    const int c4  = (tid & 15) * 4;

    const int lr = tid >> 1;
    const int lk = (tid & 1) * 4;
    const int m  = bm0 + lr;
    const float* ap = x + (size_t)(m & 31) * ((size_t)TT * DIM) + (size_t)(m >> 5) * DIM + lk;
    const float* bp = Wih + (size_t)(bn0 + lr) * DIM + lk;

    ull c2[4][8];
    #pragma unroll
    for (int i = 0; i < 4; i++)
        #pragma unroll
        for (int j = 0; j < 8; j++) c2[i][j] = 0ULL;

    float4 av = *(const float4*)ap;
    float4 bv = *(const float4*)bp;

    for (int k0 = 0; k0 < DIM; k0 += 8){
        As[lk+0][lr]=av.x; As[lk+1][lr]=av.y; As[lk+2][lr]=av.z; As[lk+3][lr]=av.w;
        Bs[lk+0][lr]=bv.x; Bs[lk+1][lr]=bv.y; Bs[lk+2][lr]=bv.z; Bs[lk+3][lr]=bv.w;
        __syncthreads();
        if (k0 + 8 < DIM){
            av = *(const float4*)(ap + k0 + 8);
            bv = *(const float4*)(bp + k0 + 8);
        }
        #pragma unroll
        for (int kk = 0; kk < 8; kk++){
            const ulonglong2* arow = (const ulonglong2*)&As[kk][tm0];
            ulonglong2 a01 = arow[0];
            ulonglong2 a23 = arow[1];
            float4 bl = *(const float4*)&Bs[kk][c4];
            float4 bh = *(const float4*)&Bs[kk][c4 + 64];
            ull bd[8];
            bd[0]=pk2(bl.x,bl.x); bd[1]=pk2(bl.y,bl.y); bd[2]=pk2(bl.z,bl.z); bd[3]=pk2(bl.w,bl.w);
            bd[4]=pk2(bh.x,bh.x); bd[5]=pk2(bh.y,bh.y); bd[6]=pk2(bh.z,bh.z); bd[7]=pk2(bh.w,bh.w);
            #pragma unroll
            for (int j = 0; j < 8; j++){
                c2[0][j] = f2fma(a01.x, bd[j], c2[0][j]);
                c2[1][j] = f2fma(a01.y, bd[j], c2[1][j]);
                c2[2][j] = f2fma(a23.x, bd[j], c2[2][j]);
                c2[3][j] = f2fma(a23.y, bd[j], c2[3][j]);
            }
        }
        __syncthreads();
    }

    float bias[8];
    #pragma unroll
    for (int j = 0; j < 8; j++){
        int n = bn0 + c4 + (j & 3) + ((j >> 2) << 6);
        bias[j] = bih[n] + bhh[n];
    }
    #pragma unroll
    for (int i = 0; i < 8; i++){
        int mg = bm0 + tm0 + i;
        size_t obase = (size_t)(mg >> 5) * ((size_t)G4 * BATCH) + (size_t)(mg & 31);
        #pragma unroll
        for (int j = 0; j < 8; j++){
            float2 p = upk(c2[i >> 1][j]);
            float v = (i & 1) ? p.y : p.x;
            int n = bn0 + c4 + (j & 3) + ((j >> 2) << 6);
            g_xg[obase + (size_t)n * BATCH] = v + bias[j];
        }
    }
}

// =====================================================================
// Kernel 2: persistent recurrence. 128 blocks x 512 threads (16 warps).
// warp = kh (k-sixteenth, 32 k each); lane = (bq = l&7, dl = l>>3).
// Thread computes 4 gates x 4 batches (bq+8j) x 32 k for dim dg=bx*4+dl.
// h staged into shared each step (coalesced); W padded rows in shared;
// single-phase k-reduction buffer [16 rows][16 kh x 33]; pointwise +
// c-state in tid<128. Single-counter grid barrier, skipped on last step;
// out store + next-step xg prefetch overlap the barrier wait.
// =====================================================================
__global__ void __launch_bounds__(RTHR) lstm_rec_kernel(
    const float* __restrict__ Whh, float* __restrict__ out)
{
    extern __shared__ float sm[];
    float* shW = sm;                       // 16 rows x 516 floats (padded)
    float* shH = sm + 16 * 516;            // 16384 floats, same layout as g_hbuf
    float* shR = shH + 16384;              // [16 rows][16 kh][33]

    const int tid = threadIdx.x;
    const int bx  = blockIdx.x;
    const int kh  = tid >> 5;              // warp id = k-sixteenth (0..15)
    const int lane= tid & 31;
    const int bq  = lane & 7;
    const int dl  = lane >> 3;

    // Load this block's 16 W_hh rows into padded shared (once).
    for (int idx = tid; idx < 16 * 128; idx += RTHR){
        int rl = idx >> 7;                 // g*4 + dloc
        int k4 = idx & 127;
        int g = rl >> 2, dloc = rl & 3;
        *(float4*)(shW + rl * 516 + k4 * 4) =
            *(const float4*)(Whh + (size_t)(g * DIM + bx * 4 + dloc) * DIM + k4 * 4);
    }

    const ulonglong2* w0 = (const ulonglong2*)(shW + (0*4 + dl) * 516 + kh * 32);
    const ulonglong2* w1 = (const ulonglong2*)(shW + (1*4 + dl) * 516 + kh * 32);
    const ulonglong2* w2 = (const ulonglong2*)(shW + (2*4 + dl) * 516 + kh * 32);
    const ulonglong2* w3 = (const ulonglong2*)(shW + (3*4 + dl) * 516 + kh * 32);
    const ulonglong2* hsh = ((const ulonglong2*)shH) + kh * 256 + bq;

    // pointwise ownership (tid < 128): (pb, pd)
    const int pb = tid & 31;
    const int pd = tid >> 5;               // valid when tid < 128
    const int dgp = bx * 4 + pd;
    const int pbh = pb >> 3;
    const int pli = pd * 8 + (pb & 7);
    float* outp = out + (size_t)pb * ((size_t)TT * DIM) + dgp;
    const float* xgb = g_xg + (size_t)pb;
    const int hwidx = (bx * 32 + pb) * 4 + pd;   // float index in g_hbuf

    float cc = 0.0f;

    // prefetch xg for t = 0
    float xv0 = 0.f, xv1 = 0.f, xv2 = 0.f, xv3 = 0.f;
    if (tid < 128){
        xv0 = __ldcg(xgb + (size_t)(0*DIM + dgp) * BATCH);
        xv1 = __ldcg(xgb + (size_t)(1*DIM + dgp) * BATCH);
        xv2 = __ldcg(xgb + (size_t)(2*DIM + dgp) * BATCH);
        xv3 = __ldcg(xgb + (size_t)(3*DIM + dgp) * BATCH);
    }
    __syncthreads();                       // W ready

    for (int t = 0; t < TT; t++){
        // ---- stage h_{t-1} into shared (coalesced, high-MLP) ----
        const float4* hsrc = (const float4*)g_hbuf[t & 1];
        float4* hdst = (float4*)shH;
        #pragma unroll
        for (int i = 0; i < 8; i++) hdst[tid + i * RTHR] = __ldcg(hsrc + tid + i * RTHR);
        __syncthreads();

        // ---- partial gates over this thread's 32-k slice, 4 b, 4 gates ----
        ull acc[4][4];
        #pragma unroll
        for (int g = 0; g < 4; g++)
            #pragma unroll
            for (int j = 0; j < 4; j++) acc[g][j] = 0ULL;

        #pragma unroll
        for (int i = 0; i < 8; i++){
            ulonglong2 h0 = hsh[i * 32];
            ulonglong2 h1 = hsh[i * 32 + 8];
            ulonglong2 h2 = hsh[i * 32 + 16];
            ulonglong2 h3 = hsh[i * 32 + 24];
            ulonglong2 v0 = w0[i], v1 = w1[i], v2 = w2[i], v3 = w3[i];
            acc[0][0]=f2fma(h0.x,v0.x,acc[0][0]); acc[0][0]=f2fma(h0.y,v0.y,acc[0][0]);
            acc[0][1]=f2fma(h1.x,v0.x,acc[0][1]); acc[0][1]=f2fma(h1.y,v0.y,acc[0][1]);
            acc[0][2]=f2fma(h2.x,v0.x,acc[0][2]); acc[0][2]=f2fma(h2.y,v0.y,acc[0][2]);
            acc[0][3]=f2fma(h3.x,v0.x,acc[0][3]); acc[0][3]=f2fma(h3.y,v0.y,acc[0][3]);
            acc[1][0]=f2fma(h0.x,v1.x,acc[1][0]); acc[1][0]=f2fma(h0.y,v1.y,acc[1][0]);
            acc[1][1]=f2fma(h1.x,v1.x,acc[1][1]); acc[1][1]=f2fma(h1.y,v1.y,acc[1][1]);
            acc[1][2]=f2fma(h2.x,v1.x,acc[1][2]); acc[1][2]=f2fma(h2.y,v1.y,acc[1][2]);
            acc[1][3]=f2fma(h3.x,v1.x,acc[1][3]); acc[1][3]=f2fma(h3.y,v1.y,acc[1][3]);
            acc[2][0]=f2fma(h0.x,v2.x,acc[2][0]); acc[2][0]=f2fma(h0.y,v2.y,acc[2][0]);
            acc[2][1]=f2fma(h1.x,v2.x,acc[2][1]); acc[2][1]=f2fma(h1.y,v2.y,acc[2][1]);
            acc[2][2]=f2fma(h2.x,v2.x,acc[2][2]); acc[2][2]=f2fma(h2.y,v2.y,acc[2][2]);
            acc[2][3]=f2fma(h3.x,v2.x,acc[2][3]); acc[2][3]=f2fma(h3.y,v2.y,acc[2][3]);
            acc[3][0]=f2fma(h0.x,v3.x,acc[3][0]); acc[3][0]=f2fma(h0.y,v3.y,acc[3][0]);
            acc[3][1]=f2fma(h1.x,v3.x,acc[3][1]); acc[3][1]=f2fma(h1.y,v3.y,acc[3][1]);
            acc[3][2]=f2fma(h2.x,v3.x,acc[3][2]); acc[3][2]=f2fma(h2.y,v3.y,acc[3][2]);
            acc[3][3]=f2fma(h3.x,v3.x,acc[3][3]); acc[3][3]=f2fma(h3.y,v3.y,acc[3][3]);
        }

        // ---- write partials: shR[(g*4+j)*528 + kh*33 + lane] ----
        #pragma unroll
        for (int g = 0; g < 4; g++)
            #pragma unroll
            for (int j = 0; j < 4; j++)
                shR[(g*4 + j) * 528 + kh * 33 + lane] = hadd(acc[g][j]);
        __syncthreads();

        float hv = 0.f;
        if (tid < 128){
            float gs[4];
            #pragma unroll
            for (int g = 0; g < 4; g++){
                const float* r = shR + (g*4 + pbh) * 528 + pli;
                float s = r[0];
                #pragma unroll
                for (int k = 1; k < 16; k++) s += r[k * 33];
                gs[g] = s;
            }
            float gi = gs[0] + xv0;
            float gf = gs[1] + xv1;
            float gg = gs[2] + xv2;
            float go = gs[3] + xv3;
            float iv = sigf(gi), fv = sigf(gf), gv = tanhfast(gg), ov = sigf(go);
            cc = fv * cc + iv * gv;
            hv = ov * tanhfast(cc);
            g_hbuf[(t + 1) & 1][hwidx] = hv;
        }

        if (t + 1 == TT){                  // last step: no barrier needed
            if (tid < 128) outp[(size_t)t * DIM] = hv;
            break;
        }

        // ---- arrival (release covers the h store) ----
        __syncthreads();
        if (tid == 0) red_release_add(&g_count, 1u);

        // ---- overlap barrier wait: out store + next xg prefetch ----
        if (tid < 128){
            outp[(size_t)t * DIM] = hv;
            const float* xt = xgb + (size_t)(t + 1) * ((size_t)G4 * BATCH);
            xv0 = __ldcg(xt + (size_t)(0*DIM + dgp) * BATCH);
            xv1 = __ldcg(xt + (size_t)(1*DIM + dgp) * BATCH);
            xv2 = __ldcg(xt + (size_t)(2*DIM + dgp) * BATCH);
            xv3 = __ldcg(xt + (size_t)(3*DIM + dgp) * BATCH);
        }

        // ---- wait for all arrivals ----
        if (tid == 0){
            const unsigned target = (unsigned)(t + 1) * NBLK;
            while (ld_acquire(&g_count) < target) { }
        }
        __syncthreads();
    }
}

// =====================================================================
extern "C" void kernel_launch(void* const* d_in, const int* in_sizes, int n_in,
                              void* d_out, int out_size)
{
    (void)in_sizes; (void)n_in; (void)out_size;
    const float* x    = (const float*)d_in[0];
    const float* Wih  = (const float*)d_in[1];
    const float* Whh  = (const float*)d_in[2];
    const float* bih  = (const float*)d_in[3];
    const float* bhh  = (const float*)d_in[4];
    float* out = (float*)d_out;

    // shW 16*516 + shH 16384 + shR 16*528 = 33088 floats = 132352 bytes
    cudaFuncSetAttribute(lstm_rec_kernel,
                         cudaFuncAttributeMaxDynamicSharedMemorySize, 132352);

    dim3 ggrid(G4 / 128, (BATCH * TT) / 128);
    gemm_xg_kernel<<<ggrid, 256>>>(x, Wih, bih, bhh);
    lstm_rec_kernel<<<NBLK, RTHR, 132352>>>(Whh, out);
}

// round 7
// speedup vs baseline: 1.5632x; 1.0320x over previous
#include <cuda_runtime.h>
#include <cstdint>

#define DIM   512
#define BATCH 32
#define TT    2048
#define G4    2048              // 4*DIM
#define NBLK  128               // persistent blocks for recurrence
#define RTHR  512

// ---------------- device scratch (no allocations allowed) ----------------
__device__ __align__(16) float g_xg[(size_t)TT * G4 * BATCH];   // [t][n][b]
__device__ __align__(16) float g_hbuf[2][DIM * BATCH];          // [d>>2][b][d&3]
__device__ unsigned g_flag[NBLK * 8];   // one flag per block, 32B apart

typedef unsigned long long ull;

// ---------------- f32x2 helpers ----------------
__device__ __forceinline__ ull f2fma(ull a, ull b, ull c){
    ull d; asm("fma.rn.f32x2 %0, %1, %2, %3;" : "=l"(d) : "l"(a), "l"(b), "l"(c)); return d;
}
__device__ __forceinline__ ull pk2(float lo, float hi){
    ull r; asm("mov.b64 %0, {%1, %2};" : "=l"(r) : "f"(lo), "f"(hi)); return r;
}
__device__ __forceinline__ float2 upk(ull v){
    float2 f; asm("mov.b64 {%0, %1}, %2;" : "=f"(f.x), "=f"(f.y) : "l"(v)); return f;
}
__device__ __forceinline__ float hadd(ull v){ float2 f = upk(v); return f.x + f.y; }

__device__ __forceinline__ float sigf(float x){ return 1.0f / (1.0f + __expf(-x)); }
__device__ __forceinline__ float tanhfast(float x){
    float e = __expf(2.0f * x);              // inf-safe at both ends
    return 1.0f - 2.0f / (e + 1.0f);
}

// ---------------- scoped sync primitives ----------------
__device__ __forceinline__ void st_release(unsigned* p, unsigned v){
    asm volatile("st.release.gpu.global.u32 [%0], %1;" :: "l"(p), "r"(v) : "memory");
}
__device__ __forceinline__ unsigned ld_acquire(unsigned* p){
    unsigned v;
    asm volatile("ld.acquire.gpu.global.u32 %0, [%1];" : "=r"(v) : "l"(p) : "memory");
    return v;
}
__device__ __forceinline__ void cpa16(unsigned dst, const void* src){
    asm volatile("cp.async.cg.shared.global [%0], [%1], 16;" :: "r"(dst), "l"(src));
}

// =====================================================================
// Kernel 1: xg[t][n][b] = sum_k x[b][t][k]*W_ih[n][k] + b_ih[n] + b_hh[n]
// M = 65536 (m = t*32 + b), N = 2048, K = 512. 128x128x8 tile, f32x2.
// Block (0,0) also re-initializes recurrence state each launch.
// =====================================================================
__global__ void __launch_bounds__(256) gemm_xg_kernel(
    const float* __restrict__ x, const float* __restrict__ Wih,
    const float* __restrict__ bih, const float* __restrict__ bhh)
{
    __shared__ float As[8][128];
    __shared__ float Bs[8][128];
    const int tid = threadIdx.x;

    if (blockIdx.x == 0 && blockIdx.y == 0){     // init (runs before rec kernel)
        for (int i = tid; i < DIM * BATCH; i += 256) g_hbuf[0][i] = 0.0f;
        for (int i = tid; i < NBLK; i += 256) g_flag[i * 8] = 0u;
    }

    const int bn0 = blockIdx.x * 128;
    const int bm0 = blockIdx.y * 128;
    const int tm0 = (tid >> 4) * 8;
    const int c4  = (tid & 15) * 4;

    const int lr = tid >> 1;
    const int lk = (tid & 1) * 4;
    const int m  = bm0 + lr;
    const float* ap = x + (size_t)(m & 31) * ((size_t)TT * DIM) + (size_t)(m >> 5) * DIM + lk;
    const float* bp = Wih + (size_t)(bn0 + lr) * DIM + lk;

    ull c2[4][8];
    #pragma unroll
    for (int i = 0; i < 4; i++)
        #pragma unroll
        for (int j = 0; j < 8; j++) c2[i][j] = 0ULL;

    float4 av = *(const float4*)ap;
    float4 bv = *(const float4*)bp;

    for (int k0 = 0; k0 < DIM; k0 += 8){
        As[lk+0][lr]=av.x; As[lk+1][lr]=av.y; As[lk+2][lr]=av.z; As[lk+3][lr]=av.w;
        Bs[lk+0][lr]=bv.x; Bs[lk+1][lr]=bv.y; Bs[lk+2][lr]=bv.z; Bs[lk+3][lr]=bv.w;
        __syncthreads();
        if (k0 + 8 < DIM){
            av = *(const float4*)(ap + k0 + 8);
            bv = *(const float4*)(bp + k0 + 8);
        }
        #pragma unroll
        for (int kk = 0; kk < 8; kk++){
            const ulonglong2* arow = (const ulonglong2*)&As[kk][tm0];
            ulonglong2 a01 = arow[0];
            ulonglong2 a23 = arow[1];
            float4 bl = *(const float4*)&Bs[kk][c4];
            float4 bh = *(const float4*)&Bs[kk][c4 + 64];
            ull bd[8];
            bd[0]=pk2(bl.x,bl.x); bd[1]=pk2(bl.y,bl.y); bd[2]=pk2(bl.z,bl.z); bd[3]=pk2(bl.w,bl.w);
            bd[4]=pk2(bh.x,bh.x); bd[5]=pk2(bh.y,bh.y); bd[6]=pk2(bh.z,bh.z); bd[7]=pk2(bh.w,bh.w);
            #pragma unroll
            for (int j = 0; j < 8; j++){
                c2[0][j] = f2fma(a01.x, bd[j], c2[0][j]);
                c2[1][j] = f2fma(a01.y, bd[j], c2[1][j]);
                c2[2][j] = f2fma(a23.x, bd[j], c2[2][j]);
                c2[3][j] = f2fma(a23.y, bd[j], c2[3][j]);
            }
        }
        __syncthreads();
    }

    float bias[8];
    #pragma unroll
    for (int j = 0; j < 8; j++){
        int n = bn0 + c4 + (j & 3) + ((j >> 2) << 6);
        bias[j] = bih[n] + bhh[n];
    }
    #pragma unroll
    for (int i = 0; i < 8; i++){
        int mg = bm0 + tm0 + i;
        size_t obase = (size_t)(mg >> 5) * ((size_t)G4 * BATCH) + (size_t)(mg & 31);
        #pragma unroll
        for (int j = 0; j < 8; j++){
            float2 p = upk(c2[i >> 1][j]);
            float v = (i & 1) ? p.y : p.x;
            int n = bn0 + c4 + (j & 3) + ((j >> 2) << 6);
            g_xg[obase + (size_t)n * BATCH] = v + bias[j];
        }
    }
}

// =====================================================================
// Kernel 2: persistent recurrence, dataflow-pipelined.
// 128 blocks x 512 threads (16 warps). FMA role: warp kh owns k-slice
// [kh*32, kh*32+32); lane = (bq = l&7, dl = l>>3); thread computes
// 4 gates x 4 batches for dim dg = bx*4+dl over its 32 k.
// Warp kh's h slice is produced by blocks kh*8..kh*8+7 only -> each warp
// polls just those 8 flags, cp.asyncs its own 4KB slice, and starts FMA
// without any block-wide pre-sync. Reduce role: warp w = (gate g=w>>2,
// dim rd=w&3), lane = batch. Owners (tid<128) update c and store h.
// =====================================================================
__global__ void __launch_bounds__(RTHR) lstm_rec_kernel(
    const float* __restrict__ Whh, float* __restrict__ out)
{
    extern __shared__ float sm[];
    float* shW = sm;                       // 16 rows x 516 floats (padded)
    float* shH = sm + 16 * 516;            // 16384 floats, layout = g_hbuf
    float* shR = shH + 16384;              // [16 rows][16 kh][33]
    float* shG = shR + 16 * 528;           // [4 gates][4 d][32 b]

    const int tid  = threadIdx.x;
    const int bx   = blockIdx.x;
    const int kh   = tid >> 5;             // warp id
    const int lane = tid & 31;
    const int bq   = lane & 7;
    const int dl   = lane >> 3;

    // Load this block's 16 W_hh rows into padded shared (once).
    for (int idx = tid; idx < 16 * 128; idx += RTHR){
        int rl = idx >> 7;                 // g*4 + dloc
        int k4 = idx & 127;
        int g = rl >> 2, dloc = rl & 3;
        *(float4*)(shW + rl * 516 + k4 * 4) =
            *(const float4*)(Whh + (size_t)(g * DIM + bx * 4 + dloc) * DIM + k4 * 4);
    }

    const ulonglong2* w0 = (const ulonglong2*)(shW + (0*4 + dl) * 516 + kh * 32);
    const ulonglong2* w1 = (const ulonglong2*)(shW + (1*4 + dl) * 516 + kh * 32);
    const ulonglong2* w2 = (const ulonglong2*)(shW + (2*4 + dl) * 516 + kh * 32);
    const ulonglong2* w3 = (const ulonglong2*)(shW + (3*4 + dl) * 516 + kh * 32);
    const ulonglong2* hsh = ((const ulonglong2*)shH) + kh * 256 + bq;

    // staging addresses for this warp's 4KB slice (256 float4)
    const unsigned shH_u32 =
        (unsigned)__cvta_generic_to_shared(shH) + (unsigned)(kh * 256 + lane) * 16u;

    // reduce role
    const int rg = kh >> 2;                // gate
    const int rd = kh & 3;                 // local dim
    const float* rp = shR + (rg * 4 + (lane >> 3)) * 528 + rd * 8 + (lane & 7);
    const size_t xoffs = (size_t)(rg * DIM + bx * 4 + rd) * BATCH + lane;

    // owner role (tid < 128)
    const int pb = tid & 31;
    const int pd = tid >> 5;
    const int dgp = bx * 4 + pd;
    float* outp = out + (size_t)pb * ((size_t)TT * DIM) + dgp;
    const int hwidx = bx * 128 + pb * 4 + pd;

    // producer flags for this warp's k-slice: blocks kh*8 .. kh*8+7
    unsigned* myflag = &g_flag[(kh * 8 + (lane & 7)) * 8];

    float cc = 0.0f;
    float hv = 0.0f;
    __syncthreads();                       // W ready

    for (int t = 0; t < TT; t++){
        // xg prefetch (independent of h; issued before everything)
        float xv = __ldcg(g_xg + (size_t)t * ((size_t)G4 * BATCH) + xoffs);

        // ---- per-warp relaxed poll: my 8 producers reached step t ----
        if (t > 0){
            if (lane < 8){
                while (ld_acquire(myflag) < (unsigned)t) { }
            }
            __syncwarp();
        }

        // ---- stage my 4KB h slice via cp.async ----
        const float4* hsrc = (const float4*)g_hbuf[t & 1] + (kh * 256 + lane);
        #pragma unroll
        for (int q = 0; q < 8; q++)
            cpa16(shH_u32 + q * 512u, hsrc + q * 32);
        asm volatile("cp.async.commit_group;");
        asm volatile("cp.async.wait_group 0;");
        __syncwarp();

        // ---- partial gates over my 32-k slice, 4 b, 4 gates ----
        ull acc[4][4];
        #pragma unroll
        for (int g = 0; g < 4; g++)
            #pragma unroll
            for (int j = 0; j < 4; j++) acc[g][j] = 0ULL;

        #pragma unroll
        for (int i = 0; i < 8; i++){
            ulonglong2 h0 = hsh[i * 32];
            ulonglong2 h1 = hsh[i * 32 + 8];
            ulonglong2 h2 = hsh[i * 32 + 16];
            ulonglong2 h3 = hsh[i * 32 + 24];
            ulonglong2 v0 = w0[i], v1 = w1[i], v2 = w2[i], v3 = w3[i];
            acc[0][0]=f2fma(h0.x,v0.x,acc[0][0]); acc[0][0]=f2fma(h0.y,v0.y,acc[0][0]);
            acc[0][1]=f2fma(h1.x,v0.x,acc[0][1]); acc[0][1]=f2fma(h1.y,v0.y,acc[0][1]);
            acc[0][2]=f2fma(h2.x,v0.x,acc[0][2]); acc[0][2]=f2fma(h2.y,v0.y,acc[0][2]);
            acc[0][3]=f2fma(h3.x,v0.x,acc[0][3]); acc[0][3]=f2fma(h3.y,v0.y,acc[0][3]);
            acc[1][0]=f2fma(h0.x,v1.x,acc[1][0]); acc[1][0]=f2fma(h0.y,v1.y,acc[1][0]);
            acc[1][1]=f2fma(h1.x,v1.x,acc[1][1]); acc[1][1]=f2fma(h1.y,v1.y,acc[1][1]);
            acc[1][2]=f2fma(h2.x,v1.x,acc[1][2]); acc[1][2]=f2fma(h2.y,v1.y,acc[1][2]);
            acc[1][3]=f2fma(h3.x,v1.x,acc[1][3]); acc[1][3]=f2fma(h3.y,v1.y,acc[1][3]);
            acc[2][0]=f2fma(h0.x,v2.x,acc[2][0]); acc[2][0]=f2fma(h0.y,v2.y,acc[2][0]);
            acc[2][1]=f2fma(h1.x,v2.x,acc[2][1]); acc[2][1]=f2fma(h1.y,v2.y,acc[2][1]);
            acc[2][2]=f2fma(h2.x,v2.x,acc[2][2]); acc[2][2]=f2fma(h2.y,v2.y,acc[2][2]);
            acc[2][3]=f2fma(h3.x,v2.x,acc[2][3]); acc[2][3]=f2fma(h3.y,v2.y,acc[2][3]);
            acc[3][0]=f2fma(h0.x,v3.x,acc[3][0]); acc[3][0]=f2fma(h0.y,v3.y,acc[3][0]);
            acc[3][1]=f2fma(h1.x,v3.x,acc[3][1]); acc[3][1]=f2fma(h1.y,v3.y,acc[3][1]);
            acc[3][2]=f2fma(h2.x,v3.x,acc[3][2]); acc[3][2]=f2fma(h2.y,v3.y,acc[3][2]);
            acc[3][3]=f2fma(h3.x,v3.x,acc[3][3]); acc[3][3]=f2fma(h3.y,v3.y,acc[3][3]);
        }

        // ---- write partials: shR[(g*4+j)*528 + kh*33 + lane] ----
        #pragma unroll
        for (int g = 0; g < 4; g++)
            #pragma unroll
            for (int j = 0; j < 4; j++)
                shR[(g*4 + j) * 528 + kh * 33 + lane] = hadd(acc[g][j]);
        __syncthreads();                   // bar1: all partials in

        // ---- reduce (warp = gate x dim, lane = batch) + nonlinearity ----
        {
            float s = xv;
            #pragma unroll
            for (int k = 0; k < 16; k++) s += rp[k * 33];
            float v = (rg == 2) ? tanhfast(s) : sigf(s);
            shG[rg * 128 + rd * 32 + lane] = v;
        }
        __syncthreads();                   // bar2: gates ready

        // ---- owners: c/h update, store h ----
        if (tid < 128){
            float iv = shG[  0 + pd * 32 + pb];
            float fv = shG[128 + pd * 32 + pb];
            float gv = shG[256 + pd * 32 + pb];
            float ov = shG[384 + pd * 32 + pb];
            cc = fv * cc + iv * gv;
            hv = ov * tanhfast(cc);
            g_hbuf[(t + 1) & 1][hwidx] = hv;
        }
        __syncthreads();                   // bar3: h stores done block-wide

        if (t + 1 < TT){
            if (tid == 0) st_release(&g_flag[bx * 8], (unsigned)(t + 1));
        }
        // out store overlaps the next step's polls
        if (tid < 128) outp[(size_t)t * DIM] = hv;
    }
}

// =====================================================================
extern "C" void kernel_launch(void* const* d_in, const int* in_sizes, int n_in,
                              void* d_out, int out_size)
{
    (void)in_sizes; (void)n_in; (void)out_size;
    const float* x    = (const float*)d_in[0];
    const float* Wih  = (const float*)d_in[1];
    const float* Whh  = (const float*)d_in[2];
    const float* bih  = (const float*)d_in[3];
    const float* bhh  = (const float*)d_in[4];
    float* out = (float*)d_out;

    // shW 16*516 + shH 16384 + shR 16*528 + shG 512 = 33600 floats = 134400 B
    cudaFuncSetAttribute(lstm_rec_kernel,
                         cudaFuncAttributeMaxDynamicSharedMemorySize, 134400);

    dim3 ggrid(G4 / 128, (BATCH * TT) / 128);
    gemm_xg_kernel<<<ggrid, 256>>>(x, Wih, bih, bhh);
    lstm_rec_kernel<<<NBLK, RTHR, 134400>>>(Whh, out);
}